// round 9
// baseline (speedup 1.0000x reference)
#include <cuda_runtime.h>
#include <cuda_bf16.h>
#include <cstdint>

// NMU forward: y[b,o] = prod_d ( M_hat[d,o]*x[b,d] + (1 - M_hat[d,o]) )
// B=16384, D=256, O=32, fp32.
//
// R9: cp.async double-buffered pipeline.
//  - block = 512 thr (16 warps); warp w owns d in [16w,16w+16), lane = o.
//  - m2[8] = packed (m[d],m[d+1]), c2[8] = packed (1-m,...) in registers.
//    hot loop: t = fma(m2, x2_raw, c2)  -> no x-1 staging transform needed.
//  - x tiles (16 rows x 256) stream through 2 smem buffers via cp.async:
//    prefetch tile t+2 while computing tile t. LDG latency paid once per CTA.
//  - grid 256, 4 tiles/CTA: all CTAs resident immediately, no waves.
//  - per-tile epilogue: 16-slab partial product, 1 output/thread, STG.32.

#define NMU_D    256
#define NMU_O    32
#define NMU_ROWS 16        // rows per tile
#define NMU_T    4         // tiles per CTA
#define NMU_NW   16        // warps per block

__device__ __forceinline__ unsigned long long f2_fma(unsigned long long a,
                                                     unsigned long long b,
                                                     unsigned long long c) {
    unsigned long long d;
    asm("fma.rn.f32x2 %0, %1, %2, %3;" : "=l"(d) : "l"(a), "l"(b), "l"(c));
    return d;
}
__device__ __forceinline__ unsigned long long f2_mul(unsigned long long a,
                                                     unsigned long long b) {
    unsigned long long d;
    asm("mul.rn.f32x2 %0, %1, %2;" : "=l"(d) : "l"(a), "l"(b));
    return d;
}
__device__ __forceinline__ unsigned long long pack2(float a, float b) {
    unsigned long long d;
    asm("mov.b64 %0, {%1, %2};" : "=l"(d)
        : "r"(__float_as_uint(a)), "r"(__float_as_uint(b)));
    return d;
}
__device__ __forceinline__ void cp16(uint32_t s, const void* g) {
    asm volatile("cp.async.cg.shared.global [%0], [%1], 16;"
                 :: "r"(s), "l"(g) : "memory");
}
#define CP_COMMIT()  asm volatile("cp.async.commit_group;" ::: "memory")
#define CP_WAIT_1()  asm volatile("cp.async.wait_group 1;" ::: "memory")

// stage one 16x256 tile (16 KB): each of 512 threads copies 32 bytes
__device__ __forceinline__ void stage_tile(const float* __restrict__ x,
                                           int tile, uint32_t dst_s,
                                           int tid) {
    const char* g = (const char*)(x + (size_t)tile * NMU_ROWS * NMU_D)
                    + (size_t)tid * 32;
    uint32_t s = dst_s + tid * 32;
    cp16(s, g);
    cp16(s + 16, g + 16);
}

__global__ void __launch_bounds__(512, 2)
nmu_kernel(const float* __restrict__ x, const float* __restrict__ M,
           float* __restrict__ out) {
    extern __shared__ float sm[];
    float* xb[2];
    xb[0] = sm;                                   // 16 KB
    xb[1] = sm + NMU_ROWS * NMU_D;                // 16 KB
    float* pw = sm + 2 * NMU_ROWS * NMU_D;        // 32 KB partials

    const int tid  = threadIdx.x;
    const int warp = tid >> 5;
    const int o    = tid & 31;
    const int d0   = warp * 16;
    const int tile0 = blockIdx.x * NMU_T;

    const uint32_t xb_s0 = (uint32_t)__cvta_generic_to_shared(xb[0]);
    const uint32_t xb_s1 = (uint32_t)__cvta_generic_to_shared(xb[1]);

    // --- prologue: prefetch tiles 0 and 1 ---
    stage_tile(x, tile0 + 0, xb_s0, tid);  CP_COMMIT();
    stage_tile(x, tile0 + 1, xb_s1, tid);  CP_COMMIT();

    // --- weights (overlap with prefetch latency) ---
    unsigned long long m2[8], c2[8];
    {
        const float* __restrict__ Mg = M + (size_t)d0 * NMU_O + o;
        #pragma unroll
        for (int k = 0; k < 8; k++) {
            float a = __saturatef(__ldg(Mg + (2 * k + 0) * NMU_O));
            float b = __saturatef(__ldg(Mg + (2 * k + 1) * NMU_O));
            m2[k] = pack2(a, b);
            c2[k] = pack2(1.0f - a, 1.0f - b);
        }
    }

    // --- pipelined tile loop ---
    #pragma unroll 1
    for (int t = 0; t < NMU_T; t++) {
        CP_WAIT_1();            // tile t landed (<=1 group still in flight)
        __syncthreads();        // make all threads' copies visible

        const float* xbuf = xb[t & 1];

        // compute 16 rows: per row 4 broadcast LDS.128 + 8 fma2 + chains
        #pragma unroll 2
        for (int r = 0; r < NMU_ROWS; r++) {
            const ulonglong2* __restrict__ ur =
                (const ulonglong2*)(xbuf + r * NMU_D + d0);
            ulonglong2 v0 = ur[0], v1 = ur[1], v2 = ur[2], v3 = ur[3];

            unsigned long long a0, a1;
            a0 = f2_fma(m2[0], v0.x, c2[0]);
            a1 = f2_fma(m2[1], v0.y, c2[1]);
            a0 = f2_mul(a0, f2_fma(m2[2], v1.x, c2[2]));
            a1 = f2_mul(a1, f2_fma(m2[3], v1.y, c2[3]));
            a0 = f2_mul(a0, f2_fma(m2[4], v2.x, c2[4]));
            a1 = f2_mul(a1, f2_fma(m2[5], v2.y, c2[5]));
            a0 = f2_mul(a0, f2_fma(m2[6], v3.x, c2[6]));
            a1 = f2_mul(a1, f2_fma(m2[7], v3.y, c2[7]));

            unsigned long long pr = f2_mul(a0, a1);
            float lo = __uint_as_float((unsigned)(pr & 0xffffffffULL));
            float hi = __uint_as_float((unsigned)(pr >> 32));
            pw[(warp * NMU_ROWS + r) * NMU_O + o] = lo * hi;  // STS.32
        }
        __syncthreads();        // pw complete; xb[t&1] free for reuse

        // prefetch tile t+2 into the buffer we just finished reading
        if (t + 2 < NMU_T)
            stage_tile(x, tile0 + t + 2, (t & 1) ? xb_s1 : xb_s0, tid);
        CP_COMMIT();            // keep group accounting uniform

        // per-tile epilogue: 1 output/thread, product over 16 warp slabs
        {
            const int row = tid >> 5;       // 0..15
            const int oo  = tid & 31;
            const float* pp = pw + row * NMU_O + oo;
            const int S = NMU_ROWS * NMU_O; // 512 floats between warp slabs
            float v[8];
            #pragma unroll
            for (int w = 0; w < 8; w++)
                v[w] = pp[(2 * w) * S] * pp[(2 * w + 1) * S];
            float b0 = (v[0] * v[1]) * (v[2] * v[3]);
            float b1 = (v[4] * v[5]) * (v[6] * v[7]);
            out[(size_t)((tile0 + t) * NMU_ROWS + row) * NMU_O + oo] = b0 * b1;
        }
        // next iteration's top barrier separates this epilogue's pw reads
        // from the next tile's pw writes
    }
}

extern "C" void kernel_launch(void* const* d_in, const int* in_sizes, int n_in,
                              void* d_out, int out_size) {
    const float* x = (const float*)d_in[0];   // [16384, 256]
    const float* M = (const float*)d_in[1];   // [256, 32]
    float* out = (float*)d_out;               // [16384, 32]

    const int B = in_sizes[0] / NMU_D;        // 16384
    const int grid = B / (NMU_ROWS * NMU_T);  // 256

    const size_t smem_bytes =
        (size_t)(2 * NMU_ROWS * NMU_D + NMU_NW * NMU_ROWS * NMU_O)
        * sizeof(float);                      // 64 KB
    cudaFuncSetAttribute(nmu_kernel,
                         cudaFuncAttributeMaxDynamicSharedMemorySize,
                         (int)smem_bytes);

    nmu_kernel<<<grid, 512, smem_bytes>>>(x, M, out);
}

// round 10
// speedup vs baseline: 1.3454x; 1.3454x over previous
#include <cuda_runtime.h>
#include <cuda_bf16.h>

// NMU forward: y[b,o] = prod_d ( M_hat[d,o]*x[b,d] + (1 - M_hat[d,o]) )
//            = prod_d ( M_hat[d,o]*(x[b,d]-1) + 1 )
// B=16384, D=256, O=32, fp32.
//
// R10 = R8 hot loop + persistent work-stealing CTAs.
//  - grid 592 (4 CTAs/SM x 148): exactly one wave, no wave quantization.
//  - 2048 tiles of 8 rows, distributed via atomic counter (init kernel zeroes
//    it every replay; output independent of distribution -> deterministic).
//  - weights m2[16] (packed (m,m) pairs) loaded ONCE per block lifetime.
//  - per tile: float4-stage u=x-1 -> 8 rows x (8 bcast LDS.128 + 16 fma2 +
//    15 mul2, 4 chains) -> packed partials -> packed mul-tree epilogue.

#define NMU_D    256
#define NMU_O    32
#define NMU_R    8         // rows per tile
#define NMU_NW   8         // warps per block
#define NMU_DPW  32        // d's per warp
#define NMU_GRID 592       // 4 * 148 SMs

#define NMU_ONE2 0x3f8000003f800000ULL

__device__ unsigned int g_tile_ctr;

__device__ __forceinline__ unsigned long long f2_fma(unsigned long long a,
                                                     unsigned long long b,
                                                     unsigned long long c) {
    unsigned long long d;
    asm("fma.rn.f32x2 %0, %1, %2, %3;" : "=l"(d) : "l"(a), "l"(b), "l"(c));
    return d;
}
__device__ __forceinline__ unsigned long long f2_mul(unsigned long long a,
                                                     unsigned long long b) {
    unsigned long long d;
    asm("mul.rn.f32x2 %0, %1, %2;" : "=l"(d) : "l"(a), "l"(b));
    return d;
}
__device__ __forceinline__ unsigned long long pack2(float a, float b) {
    unsigned long long d;
    asm("mov.b64 %0, {%1, %2};" : "=l"(d)
        : "r"(__float_as_uint(a)), "r"(__float_as_uint(b)));
    return d;
}

__global__ void nmu_init() { g_tile_ctr = NMU_GRID; }

__global__ void __launch_bounds__(256, 4)
nmu_kernel(const float* __restrict__ x, const float* __restrict__ M,
           float* __restrict__ out, int n_tiles) {
    __shared__ float xs[NMU_R * NMU_D];                        // 8 KB (x-1)
    __shared__ unsigned long long pw[NMU_NW * NMU_R * NMU_O];  // 16 KB packed
    __shared__ unsigned int s_next;

    const int tid  = threadIdx.x;
    const int warp = tid >> 5;
    const int o    = tid & 31;
    const int d0   = warp * NMU_DPW;

    // --- weights: loaded ONCE per block lifetime ---
    unsigned long long m2[16];
    {
        const float* __restrict__ Mg = M + (size_t)d0 * NMU_O + o;
        #pragma unroll
        for (int k = 0; k < 16; k++) {
            float a = __saturatef(__ldg(Mg + (2 * k + 0) * NMU_O));
            float b = __saturatef(__ldg(Mg + (2 * k + 1) * NMU_O));
            m2[k] = pack2(a, b);
        }
    }

    int tile = blockIdx.x;
    while (tile < n_tiles) {
        const int b0 = tile * NMU_R;

        // --- stage u = x - 1 (coalesced float4, 2 per thread) ---
        {
            const float4* __restrict__ xg =
                (const float4*)(x + (size_t)b0 * NMU_D);
            float4* xs4 = (float4*)xs;
            #pragma unroll
            for (int i = 0; i < (NMU_R * NMU_D / 4) / 256; i++) {   // 2 iters
                float4 v = __ldg(xg + tid + i * 256);
                v.x -= 1.0f; v.y -= 1.0f; v.z -= 1.0f; v.w -= 1.0f;
                xs4[tid + i * 256] = v;
            }
        }
        // grab next tile; ATOMG latency hides under this tile's compute
        if (tid == 0) s_next = atomicAdd(&g_tile_ctr, 1u);
        __syncthreads();   // staging visible (also: pw reads of prev epilogue
                           // done before this tile's pw writes)

        // --- compute 8 rows: 4 independent product chains per row ---
        #pragma unroll 2
        for (int r = 0; r < NMU_R; r++) {
            const ulonglong2* __restrict__ ur =
                (const ulonglong2*)(xs + r * NMU_D + d0);

            unsigned long long c0, c1, c2, c3;
            {
                ulonglong2 v0 = ur[0], v1 = ur[1];
                c0 = f2_fma(m2[0], v0.x, NMU_ONE2);
                c1 = f2_fma(m2[1], v0.y, NMU_ONE2);
                c2 = f2_fma(m2[2], v1.x, NMU_ONE2);
                c3 = f2_fma(m2[3], v1.y, NMU_ONE2);
            }
            {
                ulonglong2 v2 = ur[2], v3 = ur[3];
                c0 = f2_mul(c0, f2_fma(m2[4], v2.x, NMU_ONE2));
                c1 = f2_mul(c1, f2_fma(m2[5], v2.y, NMU_ONE2));
                c2 = f2_mul(c2, f2_fma(m2[6], v3.x, NMU_ONE2));
                c3 = f2_mul(c3, f2_fma(m2[7], v3.y, NMU_ONE2));
            }
            {
                ulonglong2 v4 = ur[4], v5 = ur[5];
                c0 = f2_mul(c0, f2_fma(m2[ 8], v4.x, NMU_ONE2));
                c1 = f2_mul(c1, f2_fma(m2[ 9], v4.y, NMU_ONE2));
                c2 = f2_mul(c2, f2_fma(m2[10], v5.x, NMU_ONE2));
                c3 = f2_mul(c3, f2_fma(m2[11], v5.y, NMU_ONE2));
            }
            {
                ulonglong2 v6 = ur[6], v7 = ur[7];
                c0 = f2_mul(c0, f2_fma(m2[12], v6.x, NMU_ONE2));
                c1 = f2_mul(c1, f2_fma(m2[13], v6.y, NMU_ONE2));
                c2 = f2_mul(c2, f2_fma(m2[14], v7.x, NMU_ONE2));
                c3 = f2_mul(c3, f2_fma(m2[15], v7.y, NMU_ONE2));
            }
            // packed per-warp partial; STS.64, 2-phase conflict-free
            pw[(warp * NMU_R + r) * NMU_O + o] =
                f2_mul(f2_mul(c0, c1), f2_mul(c2, c3));
        }
        __syncthreads();   // pw complete; s_next visible

        // --- epilogue: 1 output/thread, packed mul-tree over 8 warp slabs ---
        {
            const int row = tid >> 5;        // 0..7
            const int oo  = tid & 31;
            const unsigned long long* __restrict__ pp =
                pw + row * NMU_O + oo;
            const int S = NMU_R * NMU_O;     // 256 ull between warp slabs
            unsigned long long a0 = f2_mul(pp[0 * S], pp[1 * S]);
            unsigned long long a1 = f2_mul(pp[2 * S], pp[3 * S]);
            unsigned long long a2 = f2_mul(pp[4 * S], pp[5 * S]);
            unsigned long long a3 = f2_mul(pp[6 * S], pp[7 * S]);
            unsigned long long pr = f2_mul(f2_mul(a0, a1), f2_mul(a2, a3));
            float lo = __uint_as_float((unsigned)(pr & 0xffffffffULL));
            float hi = __uint_as_float((unsigned)(pr >> 32));
            out[(size_t)(b0 + row) * NMU_O + oo] = lo * hi;
        }

        tile = (int)s_next;   // uniform across block (smem broadcast)
    }
}

extern "C" void kernel_launch(void* const* d_in, const int* in_sizes, int n_in,
                              void* d_out, int out_size) {
    const float* x = (const float*)d_in[0];   // [16384, 256]
    const float* M = (const float*)d_in[1];   // [256, 32]
    float* out = (float*)d_out;               // [16384, 32]

    const int B = in_sizes[0] / NMU_D;        // 16384
    const int n_tiles = B / NMU_R;            // 2048

    nmu_init<<<1, 1>>>();
    nmu_kernel<<<NMU_GRID, 256>>>(x, M, out, n_tiles);
}

// round 11
// speedup vs baseline: 1.4858x; 1.1044x over previous
#include <cuda_runtime.h>
#include <cuda_bf16.h>

// NMU forward: y[b,o] = prod_d ( M_hat[d,o]*x[b,d] + (1 - M_hat[d,o]) )
//            = prod_d ( M_hat[d,o]*(x[b,d]-1) + 1 )
// B=16384, D=256, O=32, fp32.
//
// R11 = R8 structure on a register diet to reach 1536 thr/SM (3 blocks).
//  - block = 512 thr (16 warps); warp w owns d in [16w,16w+16), lane = o.
//  - m2[8] packed (m[d],m[d+1]) pairs = 16 regs; x-1 staged in smem so the
//    fma addend is the constant (1,1) -> no (1-m) register array.
//  - hot loop per row: 4 broadcast LDS.128 (2 at a time, small live set) +
//    8 fma2 + 7 mul2, 2 chains; scalar partial lo*hi -> STS.32.
//  - __launch_bounds__(512,3): force <=42 regs -> 3 CTAs/SM = 1536 threads.
//  - epilogue: 1 output/thread, product over 16 warp slabs (conflict-free).

#define NMU_D   256
#define NMU_O   32
#define NMU_R   16        // rows per block
#define NMU_NW  16        // warps per block
#define NMU_DPW 16        // d's per warp

#define NMU_ONE2 0x3f8000003f800000ULL

__device__ __forceinline__ unsigned long long f2_fma(unsigned long long a,
                                                     unsigned long long b,
                                                     unsigned long long c) {
    unsigned long long d;
    asm("fma.rn.f32x2 %0, %1, %2, %3;" : "=l"(d) : "l"(a), "l"(b), "l"(c));
    return d;
}
__device__ __forceinline__ unsigned long long f2_mul(unsigned long long a,
                                                     unsigned long long b) {
    unsigned long long d;
    asm("mul.rn.f32x2 %0, %1, %2;" : "=l"(d) : "l"(a), "l"(b));
    return d;
}
__device__ __forceinline__ unsigned long long pack2(float a, float b) {
    unsigned long long d;
    asm("mov.b64 %0, {%1, %2};" : "=l"(d)
        : "r"(__float_as_uint(a)), "r"(__float_as_uint(b)));
    return d;
}
__device__ __forceinline__ float f2_lohi_mul(unsigned long long v) {
    float lo = __uint_as_float((unsigned)(v & 0xffffffffULL));
    float hi = __uint_as_float((unsigned)(v >> 32));
    return lo * hi;
}

__global__ void __launch_bounds__(512, 3)
nmu_kernel(const float* __restrict__ x, const float* __restrict__ M,
           float* __restrict__ out) {
    __shared__ float xs[NMU_R * NMU_D];            // 16 KB (x - 1)
    __shared__ float pw[NMU_NW * NMU_R * NMU_O];   // 32 KB partials

    const int tid  = threadIdx.x;
    const int warp = tid >> 5;
    const int o    = tid & 31;
    const int b0   = blockIdx.x * NMU_R;
    const int d0   = warp * NMU_DPW;

    // --- weights: 8 packed m-pairs = 16 registers, loaded once ---
    unsigned long long m2[8];
    {
        const float* __restrict__ Mg = M + (size_t)d0 * NMU_O + o;
        #pragma unroll
        for (int k = 0; k < 8; k++) {
            float a = __saturatef(__ldg(Mg + (2 * k + 0) * NMU_O));
            float b = __saturatef(__ldg(Mg + (2 * k + 1) * NMU_O));
            m2[k] = pack2(a, b);
        }
    }

    // --- stage u = x - 1 (coalesced float4, 2 per thread) ---
    {
        const float4* __restrict__ xg = (const float4*)(x + (size_t)b0 * NMU_D);
        float4* xs4 = (float4*)xs;
        #pragma unroll
        for (int i = 0; i < (NMU_R * NMU_D / 4) / 512; i++) {   // 2 iters
            float4 v = __ldg(xg + tid + i * 512);
            v.x -= 1.0f; v.y -= 1.0f; v.z -= 1.0f; v.w -= 1.0f;
            xs4[tid + i * 512] = v;
        }
    }
    __syncthreads();

    // --- hot loop: 16 rows; 2 chains; loads 2-at-a-time (small live set) ---
    #pragma unroll 2
    for (int r = 0; r < NMU_R; r++) {
        const ulonglong2* __restrict__ ur =
            (const ulonglong2*)(xs + r * NMU_D + d0);

        unsigned long long c0, c1;
        {
            ulonglong2 v0 = ur[0], v1 = ur[1];          // d0 .. d0+7
            c0 = f2_fma(m2[0], v0.x, NMU_ONE2);
            c1 = f2_fma(m2[1], v0.y, NMU_ONE2);
            c0 = f2_mul(c0, f2_fma(m2[2], v1.x, NMU_ONE2));
            c1 = f2_mul(c1, f2_fma(m2[3], v1.y, NMU_ONE2));
        }
        {
            ulonglong2 v2 = ur[2], v3 = ur[3];          // d0+8 .. d0+15
            c0 = f2_mul(c0, f2_fma(m2[4], v2.x, NMU_ONE2));
            c1 = f2_mul(c1, f2_fma(m2[5], v2.y, NMU_ONE2));
            c0 = f2_mul(c0, f2_fma(m2[6], v3.x, NMU_ONE2));
            c1 = f2_mul(c1, f2_fma(m2[7], v3.y, NMU_ONE2));
        }

        // scalar partial for this (row, warp-chunk, o)
        pw[(warp * NMU_R + r) * NMU_O + o] = f2_lohi_mul(f2_mul(c0, c1));
    }
    __syncthreads();

    // --- epilogue: 1 cell per thread; product over 16 warp slabs ---
    {
        const int row = tid >> 5;            // 0..15
        const int oo  = tid & 31;
        const float* __restrict__ pp = pw + row * NMU_O + oo;
        const int S = NMU_R * NMU_O;         // 512 floats between warp slabs
        float v[8];
        #pragma unroll
        for (int w = 0; w < 8; w++)
            v[w] = pp[(2 * w) * S] * pp[(2 * w + 1) * S];
        float a0 = (v[0] * v[1]) * (v[2] * v[3]);
        float a1 = (v[4] * v[5]) * (v[6] * v[7]);
        out[(size_t)(b0 + row) * NMU_O + oo] = a0 * a1;
    }
}

extern "C" void kernel_launch(void* const* d_in, const int* in_sizes, int n_in,
                              void* d_out, int out_size) {
    const float* x = (const float*)d_in[0];   // [16384, 256]
    const float* M = (const float*)d_in[1];   // [256, 32]
    float* out = (float*)d_out;               // [16384, 32]

    const int B = in_sizes[0] / NMU_D;        // 16384

    nmu_kernel<<<B / NMU_R, 512>>>(x, M, out);
}